// round 3
// baseline (speedup 1.0000x reference)
#include <cuda_runtime.h>
#include <cstdint>

// EdgeConv fused, round 3.
// out[p][o] = sum_cc E[p][cc] * Wt[cc][o] + bias[o]
//   E = [gsum | x]  (gsum = raw 20-window sums of the flattened gather),
//   Wt[cc][o]   = W[o][cc] / 20                 (cc < 64)
//   Wt[cc][o]   = W[o][cc] - W[o][cc-64]        (cc >= 64)

#define BB 4
#define NN 32768
#define KK 20
#define CC 64
#define C2 128
#define OUTD 64
#define TP 128          // points per block
#define THREADS 128
#define S 132           // sE row stride in floats (multiple of 4)

// dynamic smem layout (floats)
#define OFF_WT   0                       // 128*64  = 8192
#define OFF_E    8192                    // 128*132 = 16896
#define OFF_S4   (8192 + TP * S)         // 4*320   = 1280
#define OFF_B    (OFF_S4 + 4 * 320)      // 64
#define SMEM_FLOATS (OFF_B + 64)
#define SMEM_BYTES  (SMEM_FLOATS * 4)

__device__ float g_Wt[C2 * OUTD];        // cc-major combined weights

typedef unsigned long long ull;

__device__ __forceinline__ ull ffma2(ull a, ull b, ull c) {
    ull d;
    asm("fma.rn.f32x2 %0, %1, %2, %3;" : "=l"(d) : "l"(a), "l"(b), "l"(c));
    return d;
}
__device__ __forceinline__ ull addf2(ull a, ull b) {
    ull d;
    asm("add.rn.f32x2 %0, %1, %2;" : "=l"(d) : "l"(a), "l"(b));
    return d;
}
__device__ __forceinline__ ull dup2(unsigned bits) {
    ull d;
    asm("mov.b64 %0, {%1, %1};" : "=l"(d) : "r"(bits));
    return d;
}
__device__ __forceinline__ unsigned lo32(ull v) { return (unsigned)(v & 0xffffffffu); }
__device__ __forceinline__ unsigned hi32(ull v) { return (unsigned)(v >> 32); }

// ---------------- prep: build combined cc-major weights (runs once per replay) ---------
__global__ void edgeconv_prep_kernel(const float* __restrict__ W)
{
    int i = blockIdx.x * blockDim.x + threadIdx.x;   // 64 blocks * 128 thr = 8192
    if (i < C2 * OUTD) {
        int cc = i >> 6;
        int o  = i & 63;
        float w = W[o * C2 + cc];
        if (cc < CC) w *= (1.0f / (float)KK);
        else         w -= W[o * C2 + (cc - CC)];
        g_Wt[cc * OUTD + o] = w;
    }
}

// ---------------- main fused kernel ----------------
__global__ __launch_bounds__(THREADS)
void edgeconv_fused_kernel(const float* __restrict__ x,
                           const int* __restrict__ adj,
                           const float* __restrict__ bias,
                           float* __restrict__ out)
{
    extern __shared__ __align__(16) float smem[];
    float* sWt = smem + OFF_WT;    // [cc][o], row stride 64
    float* sE  = smem + OFF_E;     // [p][chunk-swizzled cc], row stride S
    float* sS4 = smem + OFF_S4;    // per-warp scratch, 320 each
    float* sB  = smem + OFF_B;

    const int tid = threadIdx.x;
    const int wid = tid >> 5;
    const int lid = tid & 31;
    const int gp0 = blockIdx.x * TP;
    const int b   = gp0 >> 15;                 // tiles never straddle batches
    const int n0  = gp0 & (NN - 1);

    // ---- fill sWt coalesced from the prepped global (conflict-free float4) ----
    {
        const float4* src = (const float4*)g_Wt;
        float4* dst = (float4*)sWt;
        #pragma unroll
        for (int i = tid; i < (C2 * OUTD) / 4; i += THREADS) dst[i] = src[i];
    }
    if (tid < OUTD) sB[tid] = bias[tid];

    // ---- gather + window-sum: warp handles points [32*wid, 32*wid+32) ----
    const float4* __restrict__ xb4 = (const float4*)(x + (size_t)b * NN * CC);
    const float2* __restrict__ xb2 = (const float2*)(x + (size_t)b * NN * CC);
    float* __restrict__ sS4w = sS4 + wid * 320;

    const int q  = lid & 15;
    const int hh = lid >> 4;

    #pragma unroll 1
    for (int g = 0; g < 4; ++g) {
        // prefetch adj for 8 points
        int a[8];
        #pragma unroll
        for (int pi = 0; pi < 8; ++pi) {
            int gp = gp0 + 32 * wid + 8 * g + pi;
            a[pi] = (lid < KK) ? adj[(size_t)gp * KK + lid] : 0;
        }

        #pragma unroll 1
        for (int pi = 0; pi < 8; ++pi) {
            const int p = 32 * wid + 8 * g + pi;
            const int n = n0 + p;

            // 10 iterations: rows 2i (lanes 0-15) and 2i+1 (lanes 16-31)
            #pragma unroll
            for (int i = 0; i < 10; ++i) {
                int r   = 2 * i + hh;
                int nbr = __shfl_sync(0xffffffffu, a[pi], r);
                float4 v = xb4[nbr * 16 + q];
                sS4w[32 * i + lid] = (v.x + v.y) + (v.z + v.w);
            }
            __syncwarp();

            // gsum[2l] = s4[10l..10l+4], gsum[2l+1] = s4[10l+5..10l+9]
            float2 r0 = *(const float2*)&sS4w[10 * lid + 0];
            float2 r1 = *(const float2*)&sS4w[10 * lid + 2];
            float2 r2 = *(const float2*)&sS4w[10 * lid + 4];
            float2 r3 = *(const float2*)&sS4w[10 * lid + 6];
            float2 r4 = *(const float2*)&sS4w[10 * lid + 8];
            float acc0 = ((r0.x + r0.y) + (r1.x + r1.y)) + r2.x;
            float acc1 = (r2.y + (r3.x + r3.y)) + (r4.x + r4.y);

            float2 xv = xb2[n * 32 + lid];

            // write E row p with chunk-XOR swizzle (psi depends only on p)
            const int psi = (p >> 3) & 3;
            const int k   = lid >> 1;
            const int h2  = (lid & 1) << 1;
            float2 g2; g2.x = acc0; g2.y = acc1;
            *(float2*)&sE[p * S + ((k ^ psi) << 2) + h2] = g2;
            float2 xw; xw.x = xv.x; xw.y = xv.y;
            *(float2*)&sE[p * S + ((16 + (k ^ psi)) << 2) + h2] = xw;

            __syncwarp();   // protect sS4 WAR
        }
    }

    __syncthreads();

    // ---- GEMM: thread tile 8 points x 8 outputs, f32x2 pairs along o ----
    const int oo = (tid >> 2) & 7;                    // output group: o = 8*oo..8*oo+7
    const int po = (tid & 3) + ((tid >> 5) << 2);     // point group:  p = 8*po..8*po+7
    const int psi = po & 3;

    ull acc[8][4];
    #pragma unroll
    for (int i = 0; i < 8; ++i)
        #pragma unroll
        for (int j = 0; j < 4; ++j) acc[i][j] = 0ULL;

    const float* eBase = sE + (8 * po) * S;
    const float* wBase = sWt + 8 * oo;

    #pragma unroll 1
    for (int it = 0; it < 32; ++it) {                 // 4 cc per iteration
        const int eoff = (it ^ psi) << 2;
        ulonglong2 e[8];
        #pragma unroll
        for (int pp = 0; pp < 8; ++pp)
            e[pp] = *(const ulonglong2*)(eBase + pp * S + eoff);

        #pragma unroll
        for (int j = 0; j < 4; ++j) {
            const float* wr = wBase + (4 * it + j) * OUTD;
            ulonglong2 w0 = *(const ulonglong2*)wr;        // o: 8oo+0..3
            ulonglong2 w1 = *(const ulonglong2*)(wr + 4);  // o: 8oo+4..7

            #pragma unroll
            for (int pp = 0; pp < 8; ++pp) {
                unsigned bits = (j == 0) ? lo32(e[pp].x)
                              : (j == 1) ? hi32(e[pp].x)
                              : (j == 2) ? lo32(e[pp].y)
                                         : hi32(e[pp].y);
                ull e2 = dup2(bits);
                acc[pp][0] = ffma2(w0.x, e2, acc[pp][0]);
                acc[pp][1] = ffma2(w0.y, e2, acc[pp][1]);
                acc[pp][2] = ffma2(w1.x, e2, acc[pp][2]);
                acc[pp][3] = ffma2(w1.y, e2, acc[pp][3]);
            }
        }
    }

    // ---- epilogue: bias + store (acc pairs are (o even, o odd) -> contiguous) ----
    ulonglong2 bb0 = *(const ulonglong2*)(sB + 8 * oo);
    ulonglong2 bb1 = *(const ulonglong2*)(sB + 8 * oo + 4);
    #pragma unroll
    for (int pp = 0; pp < 8; ++pp) {
        int p = 8 * po + pp;
        ulonglong2 r0, r1;
        r0.x = addf2(acc[pp][0], bb0.x);
        r0.y = addf2(acc[pp][1], bb0.y);
        r1.x = addf2(acc[pp][2], bb1.x);
        r1.y = addf2(acc[pp][3], bb1.y);
        float* op = out + (size_t)(gp0 + p) * OUTD + 8 * oo;
        *(ulonglong2*)op       = r0;
        *(ulonglong2*)(op + 4) = r1;
    }
}

extern "C" void kernel_launch(void* const* d_in, const int* in_sizes, int n_in,
                              void* d_out, int out_size)
{
    (void)in_sizes; (void)n_in; (void)out_size;
    const float* x    = (const float*)d_in[0];
    const int*   adj  = (const int*)d_in[1];
    const float* W    = (const float*)d_in[2];
    const float* bias = (const float*)d_in[3];
    float* out = (float*)d_out;

    cudaFuncSetAttribute(edgeconv_fused_kernel,
                         cudaFuncAttributeMaxDynamicSharedMemorySize, SMEM_BYTES);

    edgeconv_prep_kernel<<<64, 128>>>(W);
    const int tiles = (BB * NN) / TP;   // 1024
    edgeconv_fused_kernel<<<tiles, THREADS, SMEM_BYTES>>>(x, adj, bias, out);
}

// round 5
// speedup vs baseline: 1.3351x; 1.3351x over previous
#include <cuda_runtime.h>
#include <cuda_bf16.h>
#include <cstdint>

// EdgeConv fused, round 5: precomputed chunk-sums + mma.sync bf16 split GEMM.
// out[p][o] = sum_cc E[p][cc] * Wt[cc][o] + bias[o]
//   E = [gsum | x], Wt[cc<64] = W[o][cc]/20, Wt[cc>=64] = W[o][cc]-W[o][cc-64]
//   gsum[c] = sum_{q=5c}^{5c+4} xs4[adj[q/16]][q%16],  xs4[r][m] = sum_t x[r][4m+t]
// Precision: E,Wt split bf16 hi+lo; D = Ah*Bh + Al*Bh + Ah*Bl (fp32 accum regs).

#define BB 4
#define NN 32768
#define KK 20
#define CC 64
#define C2 128
#define OUTD 64
#define TP 128
#define THREADS 256
#define WS 136            // bf16 row stride (272B) for A and W smem images

// smem byte offsets
#define OFF_W_HI  0
#define OFF_W_LO  17408
#define OFF_A_HI  34816
#define OFF_A_LO  69632
#define OFF_SCR   104448         // 8 warps x 2 buffers x 352 floats
#define OFF_BIAS  126976
#define SMEM_BYTES (OFF_BIAS + 256)

__device__ float g_xs4[BB * NN * 16];                     // 8 MB chunk-sum table
__device__ __align__(16) unsigned short g_Whi[OUTD * WS];
__device__ __align__(16) unsigned short g_Wlo[OUTD * WS];

// ---------------- helpers ----------------
__device__ __forceinline__ unsigned smem_u32(const void* p) {
    unsigned a;
    asm("{ .reg .u64 t; cvta.to.shared.u64 t, %1; cvt.u32.u64 %0, t; }" : "=r"(a) : "l"(p));
    return a;
}
__device__ __forceinline__ void ldsm4(unsigned* r, unsigned addr) {
    asm volatile("ldmatrix.sync.aligned.m8n8.x4.shared.b16 {%0,%1,%2,%3}, [%4];"
                 : "=r"(r[0]), "=r"(r[1]), "=r"(r[2]), "=r"(r[3]) : "r"(addr));
}
__device__ __forceinline__ void mma16816(float* d, const unsigned* a,
                                         unsigned b0, unsigned b1) {
    asm volatile(
        "mma.sync.aligned.m16n8k16.row.col.f32.bf16.bf16.f32 "
        "{%0,%1,%2,%3}, {%4,%5,%6,%7}, {%8,%9}, {%0,%1,%2,%3};"
        : "+f"(d[0]), "+f"(d[1]), "+f"(d[2]), "+f"(d[3])
        : "r"(a[0]), "r"(a[1]), "r"(a[2]), "r"(a[3]), "r"(b0), "r"(b1));
}
__device__ __forceinline__ unsigned pack_hi(float a, float b, float& ra, float& rb) {
    __nv_bfloat16 ha = __float2bfloat16(a), hb = __float2bfloat16(b);
    ra = a - __bfloat162float(ha);
    rb = b - __bfloat162float(hb);
    return ((unsigned)__bfloat16_as_ushort(hb) << 16) | (unsigned)__bfloat16_as_ushort(ha);
}
__device__ __forceinline__ unsigned pack_lo(float ra, float rb) {
    __nv_bfloat16 la = __float2bfloat16(ra), lb = __float2bfloat16(rb);
    return ((unsigned)__bfloat16_as_ushort(lb) << 16) | (unsigned)__bfloat16_as_ushort(la);
}

// ---------------- prep 1: xs4 chunk-sum table ----------------
// warp handles 2 rows: lanes 0-15 -> row A, 16-31 -> row B; fully coalesced.
__global__ void edgeconv_xs4_kernel(const float* __restrict__ x)
{
    int wid = threadIdx.x >> 5, lid = threadIdx.x & 31;
    int row = blockIdx.x * 16 + wid * 2 + (lid >> 4);     // global row in [0, B*N)
    const float4* __restrict__ x4 = (const float4*)x;
    float4 v = x4[(size_t)row * 16 + (lid & 15)];
    g_xs4[(size_t)row * 16 + (lid & 15)] = (v.x + v.y) + (v.z + v.w);
}

// ---------------- prep 2: combined weights -> bf16 hi/lo, padded rows ----------------
__global__ void edgeconv_prepw_kernel(const float* __restrict__ W)
{
    int i = blockIdx.x * blockDim.x + threadIdx.x;
    if (i < OUTD * C2) {
        int o = i >> 7, cc = i & 127;
        float w = W[o * C2 + cc];
        if (cc < CC) w *= (1.0f / (float)KK);
        else         w -= W[o * C2 + (cc - CC)];
        __nv_bfloat16 h = __float2bfloat16(w);
        __nv_bfloat16 l = __float2bfloat16(w - __bfloat162float(h));
        g_Whi[o * WS + cc] = __bfloat16_as_ushort(h);
        g_Wlo[o * WS + cc] = __bfloat16_as_ushort(l);
    }
}

// ---------------- main fused kernel ----------------
__global__ __launch_bounds__(THREADS, 1)
void edgeconv_fused_kernel(const float* __restrict__ x,
                           const int* __restrict__ adj,
                           const float* __restrict__ bias,
                           float* __restrict__ out)
{
    extern __shared__ __align__(16) char smem[];
    const unsigned smem_base = smem_u32(smem);

    const int tid = threadIdx.x;
    const int wid = tid >> 5;
    const int lid = tid & 31;
    const int gp0 = blockIdx.x * TP;
    const int b   = gp0 >> 15;             // tiles never straddle batches
    const int n0  = gp0 & (NN - 1);

    // ---- copy prepped W images + bias ----
    {
        const uint4* sh = (const uint4*)g_Whi;
        const uint4* sl = (const uint4*)g_Wlo;
        uint4* dh = (uint4*)(smem + OFF_W_HI);
        uint4* dl = (uint4*)(smem + OFF_W_LO);
        #pragma unroll
        for (int i = tid; i < (OUTD * WS) / 8; i += THREADS) { dh[i] = sh[i]; dl[i] = sl[i]; }
    }
    if (tid < OUTD) ((float*)(smem + OFF_BIAS))[tid] = bias[tid];

    // ---- gather: warp owns points [16*wid, 16*wid+16), pipelined 1 ahead ----
    const float2* __restrict__ xs4_2 = (const float2*)g_xs4 + (size_t)b * NN * 8;
    const float2* __restrict__ xb2   = (const float2*)(x + (size_t)b * NN * CC);
    float* __restrict__ scrw = (float*)(smem + OFF_SCR) + wid * 704;

    int a[16];
    #pragma unroll
    for (int pi = 0; pi < 16; ++pi) {
        int gp = gp0 + 16 * wid + pi;
        a[pi] = (lid < KK) ? adj[(size_t)gp * KK + lid] : 0;
    }

    const int jq = lid >> 3;            // 0..3: row within LDG quad
    const int ch = lid & 7;             // chunk pair

    float2 vc[5], vn[5];
    #pragma unroll
    for (int i = 0; i < 5; ++i) {
        int nbr = __shfl_sync(0xffffffffu, a[0], 4 * i + jq);
        vc[i] = xs4_2[(size_t)nbr * 8 + ch];
    }

    #pragma unroll
    for (int pi = 0; pi < 16; ++pi) {
        float* buf = scrw + (pi & 1) * 352;

        // scatter s4 values: q = 64i + 16*(lid>>3) + 2*(lid&7); addr = 35*(q>>5)+(q&31)
        #pragma unroll
        for (int i = 0; i < 5; ++i) {
            int q = 64 * i + 16 * jq + 2 * ch;
            int addr = 35 * (q >> 5) + (q & 31);
            buf[addr]     = vc[i].x;
            buf[addr + 1] = vc[i].y;
        }

        if (pi < 15) {
            #pragma unroll
            for (int i = 0; i < 5; ++i) {
                int nbr = __shfl_sync(0xffffffffu, a[pi + 1], 4 * i + jq);
                vn[i] = xs4_2[(size_t)nbr * 8 + ch];
            }
        }
        __syncwarp();

        // lane computes gsum for cc = 2*lid, 2*lid+1
        const int q0 = 10 * lid;
        float acc0 = 0.0f, acc1 = 0.0f;
        #pragma unroll
        for (int t = 0; t < 5; ++t) {
            int q = q0 + t;
            acc0 += buf[35 * (q >> 5) + (q & 31)];
        }
        #pragma unroll
        for (int t = 5; t < 10; ++t) {
            int q = q0 + t;
            acc1 += buf[35 * (q >> 5) + (q & 31)];
        }

        const int p = 16 * wid + pi;
        float2 xv = xb2[(size_t)(n0 + p) * 32 + lid];

        float rg0, rg1, rx0, rx1;
        unsigned hp_g = pack_hi(acc0, acc1, rg0, rg1);
        unsigned hp_x = pack_hi(xv.x, xv.y, rx0, rx1);
        unsigned lp_g = pack_lo(rg0, rg1);
        unsigned lp_x = pack_lo(rx0, rx1);

        unsigned eoff = (unsigned)p * (WS * 2) + (unsigned)lid * 4;   // bytes
        *(unsigned*)(smem + OFF_A_HI + eoff)       = hp_g;
        *(unsigned*)(smem + OFF_A_LO + eoff)       = lp_g;
        *(unsigned*)(smem + OFF_A_HI + eoff + 128) = hp_x;
        *(unsigned*)(smem + OFF_A_LO + eoff + 128) = lp_x;

        #pragma unroll
        for (int i = 0; i < 5; ++i) vc[i] = vn[i];
        __syncwarp();     // protect buf WAR (reuse at pi+2)
    }

    __syncthreads();

    // ---- GEMM: warps 4M x 2N, warp tile 32x32, K=128, bf16 3-product split ----
    const int mg = wid & 3;             // row group: 32*mg
    const int ng = wid >> 2;            // col group: 32*ng
    const int lrow = (lid & 7) + 8 * ((lid >> 3) & 1);   // ldmatrix row 0..15
    const unsigned lkof = (lid >> 4) * 16;               // +16B for k8-15 mats

    const unsigned aHi = smem_base + OFF_A_HI + (32 * mg + lrow) * (WS * 2) + lkof;
    const unsigned aLo = aHi + (OFF_A_LO - OFF_A_HI);
    const unsigned bHi = smem_base + OFF_W_HI + (32 * ng + (lid & 15)) * (WS * 2) + lkof;
    const unsigned bLo = bHi + (OFF_W_LO - OFF_W_HI);

    float d[2][4][4];
    #pragma unroll
    for (int mt = 0; mt < 2; ++mt)
        #pragma unroll
        for (int nt = 0; nt < 4; ++nt)
            #pragma unroll
            for (int e = 0; e < 4; ++e) d[mt][nt][e] = 0.0f;

    #pragma unroll 2
    for (int ks = 0; ks < 8; ++ks) {
        const unsigned ko = ks * 32;
        unsigned ah[2][4], al[2][4];
        ldsm4(ah[0], aHi + ko);
        ldsm4(ah[1], aHi + 16 * (WS * 2) + ko);
        ldsm4(al[0], aLo + ko);
        ldsm4(al[1], aLo + 16 * (WS * 2) + ko);

        unsigned bh01[4], bh23[4], bl01[4], bl23[4];
        ldsm4(bh01, bHi + ko);
        ldsm4(bh23, bHi + 16 * (WS * 2) + ko);
        ldsm4(bl01, bLo + ko);
        ldsm4(bl23, bLo + 16 * (WS * 2) + ko);

        // ntile frags: nt0={r0,r2}, nt1={r1,r3} of the n0-15 mat; nt2,nt3 from n16-31
        unsigned bhf[4][2] = {{bh01[0], bh01[2]}, {bh01[1], bh01[3]},
                              {bh23[0], bh23[2]}, {bh23[1], bh23[3]}};
        unsigned blf[4][2] = {{bl01[0], bl01[2]}, {bl01[1], bl01[3]},
                              {bl23[0], bl23[2]}, {bl23[1], bl23[3]}};

        #pragma unroll
        for (int mt = 0; mt < 2; ++mt) {
            #pragma unroll
            for (int nt = 0; nt < 4; ++nt) {
                mma16816(d[mt][nt], ah[mt], bhf[nt][0], bhf[nt][1]);
                mma16816(d[mt][nt], al[mt], bhf[nt][0], bhf[nt][1]);
                mma16816(d[mt][nt], ah[mt], blf[nt][0], blf[nt][1]);
            }
        }
    }

    // ---- epilogue: bias + store (fragment rows g, g+8; cols 2*(lid&3)) ----
    const float* sBias = (const float*)(smem + OFF_BIAS);
    const int g = lid >> 2;
    const int oc = 2 * (lid & 3);
    #pragma unroll
    for (int mt = 0; mt < 2; ++mt) {
        const int prow = gp0 + 32 * mg + 16 * mt + g;
        #pragma unroll
        for (int nt = 0; nt < 4; ++nt) {
            const int o = 32 * ng + 8 * nt + oc;
            float2 bb = *(const float2*)&sBias[o];
            float2 r0, r1;
            r0.x = d[mt][nt][0] + bb.x;  r0.y = d[mt][nt][1] + bb.y;
            r1.x = d[mt][nt][2] + bb.x;  r1.y = d[mt][nt][3] + bb.y;
            *(float2*)&out[(size_t)prow * OUTD + o]       = r0;
            *(float2*)&out[(size_t)(prow + 8) * OUTD + o] = r1;
        }
    }
}

extern "C" void kernel_launch(void* const* d_in, const int* in_sizes, int n_in,
                              void* d_out, int out_size)
{
    (void)in_sizes; (void)n_in; (void)out_size;
    const float* x    = (const float*)d_in[0];
    const int*   adj  = (const int*)d_in[1];
    const float* W    = (const float*)d_in[2];
    const float* bias = (const float*)d_in[3];
    float* out = (float*)d_out;

    cudaFuncSetAttribute(edgeconv_fused_kernel,
                         cudaFuncAttributeMaxDynamicSharedMemorySize, SMEM_BYTES);

    edgeconv_xs4_kernel<<<(BB * NN) / 16, 256>>>(x);
    edgeconv_prepw_kernel<<<32, 256>>>(W);
    const int tiles = (BB * NN) / TP;   // 1024
    edgeconv_fused_kernel<<<tiles, THREADS, SMEM_BYTES>>>(x, adj, bias, out);
}

// round 6
// speedup vs baseline: 1.5887x; 1.1899x over previous
#include <cuda_runtime.h>
#include <cuda_bf16.h>
#include <cstdint>

// EdgeConv fused, round 6: 2 CTAs/SM via smem diet (XOR-swizzled images,
// single-buffer scratch). Math identical to round 5:
// out[p][o] = sum_cc E[p][cc] * Wt[cc][o] + bias[o]
//   E = [gsum | x], Wt[cc<64] = W[o][cc]/20, Wt[cc>=64] = W[o][cc]-W[o][cc-64]
//   gsum via precomputed 4-chunk sums xs4; bf16 hi/lo split, 3-term mma.sync.

#define BB 4
#define NN 32768
#define KK 20
#define CC 64
#define C2 128
#define OUTD 64
#define TP 128
#define THREADS 256

// rows are natural 256B (128 bf16); 16B chunk swizzle: k' = (k&8)|((k^row)&7)
#define ROWB 256

// smem byte offsets
#define OFF_W_HI  0               // 64*256  = 16384
#define OFF_W_LO  16384
#define OFF_A_HI  32768           // 128*256 = 32768
#define OFF_A_LO  65536
#define OFF_SCR   98304           // 8 warps x 352 floats = 11264
#define OFF_BIAS  109568
#define SMEM_BYTES (OFF_BIAS + 256)   // 109824

__device__ float g_xs4[BB * NN * 16];                      // 8 MB chunk-sum table
__device__ __align__(16) unsigned short g_Whi[OUTD * C2];  // swizzled images
__device__ __align__(16) unsigned short g_Wlo[OUTD * C2];

// ---------------- helpers ----------------
__device__ __forceinline__ unsigned smem_u32(const void* p) {
    unsigned a;
    asm("{ .reg .u64 t; cvta.to.shared.u64 t, %1; cvt.u32.u64 %0, t; }" : "=r"(a) : "l"(p));
    return a;
}
__device__ __forceinline__ void ldsm4(unsigned* r, unsigned addr) {
    asm volatile("ldmatrix.sync.aligned.m8n8.x4.shared.b16 {%0,%1,%2,%3}, [%4];"
                 : "=r"(r[0]), "=r"(r[1]), "=r"(r[2]), "=r"(r[3]) : "r"(addr));
}
__device__ __forceinline__ void mma16816(float* d, const unsigned* a,
                                         unsigned b0, unsigned b1) {
    asm volatile(
        "mma.sync.aligned.m16n8k16.row.col.f32.bf16.bf16.f32 "
        "{%0,%1,%2,%3}, {%4,%5,%6,%7}, {%8,%9}, {%0,%1,%2,%3};"
        : "+f"(d[0]), "+f"(d[1]), "+f"(d[2]), "+f"(d[3])
        : "r"(a[0]), "r"(a[1]), "r"(a[2]), "r"(a[3]), "r"(b0), "r"(b1));
}
__device__ __forceinline__ unsigned pack_hi(float a, float b, float& ra, float& rb) {
    __nv_bfloat16 ha = __float2bfloat16(a), hb = __float2bfloat16(b);
    ra = a - __bfloat162float(ha);
    rb = b - __bfloat162float(hb);
    return ((unsigned)__bfloat16_as_ushort(hb) << 16) | (unsigned)__bfloat16_as_ushort(ha);
}
__device__ __forceinline__ unsigned pack_lo(float ra, float rb) {
    __nv_bfloat16 la = __float2bfloat16(ra), lb = __float2bfloat16(rb);
    return ((unsigned)__bfloat16_as_ushort(lb) << 16) | (unsigned)__bfloat16_as_ushort(la);
}
// swizzled byte offset of 16B chunk k in row r (row stride 256B)
__device__ __forceinline__ unsigned swz(int r, int k) {
    return (unsigned)(r * ROWB + (((k & 8) | ((k ^ r) & 7)) << 4));
}

// ---------------- prep 1: xs4 chunk-sum table (64B read / 16B write per thread) ----
__global__ void edgeconv_xs4_kernel(const float* __restrict__ x)
{
    int t = blockIdx.x * blockDim.x + threadIdx.x;   // one float4 of output
    const float4* __restrict__ x4 = (const float4*)x;
    float4 v0 = x4[(size_t)t * 4 + 0];
    float4 v1 = x4[(size_t)t * 4 + 1];
    float4 v2 = x4[(size_t)t * 4 + 2];
    float4 v3 = x4[(size_t)t * 4 + 3];
    float4 o;
    o.x = (v0.x + v0.y) + (v0.z + v0.w);
    o.y = (v1.x + v1.y) + (v1.z + v1.w);
    o.z = (v2.x + v2.y) + (v2.z + v2.w);
    o.w = (v3.x + v3.y) + (v3.z + v3.w);
    ((float4*)g_xs4)[t] = o;
}

// ---------------- prep 2: combined weights -> bf16 hi/lo swizzled images ----------
__global__ void edgeconv_prepw_kernel(const float* __restrict__ W)
{
    int i = blockIdx.x * blockDim.x + threadIdx.x;
    if (i < OUTD * C2) {
        int o = i >> 7, cc = i & 127;
        float w = W[o * C2 + cc];
        if (cc < CC) w *= (1.0f / (float)KK);
        else         w -= W[o * C2 + (cc - CC)];
        __nv_bfloat16 h = __float2bfloat16(w);
        __nv_bfloat16 l = __float2bfloat16(w - __bfloat162float(h));
        int k = cc >> 3;
        unsigned byteoff = swz(o, k) + ((cc & 7) << 1);
        g_Whi[byteoff >> 1] = __bfloat16_as_ushort(h);
        g_Wlo[byteoff >> 1] = __bfloat16_as_ushort(l);
    }
}

// ---------------- main fused kernel ----------------
__global__ __launch_bounds__(THREADS, 2)
void edgeconv_fused_kernel(const float* __restrict__ x,
                           const int* __restrict__ adj,
                           const float* __restrict__ bias,
                           float* __restrict__ out)
{
    extern __shared__ __align__(16) char smem[];
    const unsigned smem_base = smem_u32(smem);

    const int tid = threadIdx.x;
    const int wid = tid >> 5;
    const int lid = tid & 31;
    const int gp0 = blockIdx.x * TP;
    const int b   = gp0 >> 15;             // tiles never straddle batches
    const int n0  = gp0 & (NN - 1);

    // ---- copy prepped W images (already swizzled, flat copy) + bias ----
    {
        const uint4* sh = (const uint4*)g_Whi;
        const uint4* sl = (const uint4*)g_Wlo;
        uint4* dh = (uint4*)(smem + OFF_W_HI);
        uint4* dl = (uint4*)(smem + OFF_W_LO);
        #pragma unroll
        for (int i = tid; i < (OUTD * C2) / 8; i += THREADS) { dh[i] = sh[i]; dl[i] = sl[i]; }
    }
    if (tid < OUTD) ((float*)(smem + OFF_BIAS))[tid] = bias[tid];

    // ---- gather: warp owns points [16*wid, 16*wid+16), LDGs pipelined 1 ahead ----
    const float2* __restrict__ xs4_2 = (const float2*)g_xs4 + (size_t)b * NN * 8;
    const float2* __restrict__ xb2   = (const float2*)(x + (size_t)b * NN * CC);
    float* __restrict__ buf = (float*)(smem + OFF_SCR) + wid * 352;

    int a[16];
    #pragma unroll
    for (int pi = 0; pi < 16; ++pi) {
        int gp = gp0 + 16 * wid + pi;
        a[pi] = (lid < KK) ? adj[(size_t)gp * KK + lid] : 0;
    }

    const int jq = lid >> 3;            // 0..3: row within LDG quad
    const int ch = lid & 7;             // chunk pair

    float2 vc[5], vn[5];
    #pragma unroll
    for (int i = 0; i < 5; ++i) {
        int nbr = __shfl_sync(0xffffffffu, a[0], 4 * i + jq);
        vc[i] = xs4_2[(size_t)nbr * 8 + ch];
    }

    #pragma unroll 1
    for (int pi = 0; pi < 16; ++pi) {
        // scatter s4 values: q = 64i + 16*jq + 2*ch; addr = 35*(q>>5)+(q&31)
        #pragma unroll
        for (int i = 0; i < 5; ++i) {
            int q = 64 * i + 16 * jq + 2 * ch;
            int addr = 35 * (q >> 5) + (q & 31);
            buf[addr]     = vc[i].x;
            buf[addr + 1] = vc[i].y;
        }

        if (pi < 15) {
            #pragma unroll
            for (int i = 0; i < 5; ++i) {
                int nbr = __shfl_sync(0xffffffffu, a[pi + 1], 4 * i + jq);
                vn[i] = xs4_2[(size_t)nbr * 8 + ch];
            }
        }
        __syncwarp();

        // lane computes gsum for cc = 2*lid, 2*lid+1
        const int q0 = 10 * lid;
        float acc0 = 0.0f, acc1 = 0.0f;
        #pragma unroll
        for (int t = 0; t < 5; ++t) {
            int q = q0 + t;
            acc0 += buf[35 * (q >> 5) + (q & 31)];
        }
        #pragma unroll
        for (int t = 5; t < 10; ++t) {
            int q = q0 + t;
            acc1 += buf[35 * (q >> 5) + (q & 31)];
        }

        const int p = 16 * wid + pi;
        float2 xv = xb2[(size_t)(n0 + p) * 32 + lid];

        float rg0, rg1, rx0, rx1;
        unsigned hp_g = pack_hi(acc0, acc1, rg0, rg1);
        unsigned hp_x = pack_hi(xv.x, xv.y, rx0, rx1);
        unsigned lp_g = pack_lo(rg0, rg1);
        unsigned lp_x = pack_lo(rx0, rx1);

        // A image: row p, chunk k = lid>>2 (gsum) / 8+(lid>>2) (x), offset (lid&3)*4
        const int w4 = (lid & 3) << 2;
        unsigned offg = swz(p, lid >> 2)       + w4;
        unsigned offx = swz(p, 8 + (lid >> 2)) + w4;
        *(unsigned*)(smem + OFF_A_HI + offg) = hp_g;
        *(unsigned*)(smem + OFF_A_LO + offg) = lp_g;
        *(unsigned*)(smem + OFF_A_HI + offx) = hp_x;
        *(unsigned*)(smem + OFF_A_LO + offx) = lp_x;

        #pragma unroll
        for (int i = 0; i < 5; ++i) vc[i] = vn[i];
        __syncwarp();     // protect buf WAR before next scatter
    }

    __syncthreads();

    // ---- GEMM: warps 4M x 2N, warp tile 32x32, K=128, bf16 3-product split ----
    const int mg = wid & 3;
    const int ng = wid >> 2;
    const int lrow  = (lid & 7) + 8 * ((lid >> 3) & 1);  // row within 16-row mat pair
    const int khalf = lid >> 4;                          // 0/1: k chunk select

    const int rA0 = 32 * mg + lrow;
    const int rB0 = 32 * ng + (lid & 15);

    float d[2][4][4];
    #pragma unroll
    for (int mt = 0; mt < 2; ++mt)
        #pragma unroll
        for (int nt = 0; nt < 4; ++nt)
            #pragma unroll
            for (int e = 0; e < 4; ++e) d[mt][nt][e] = 0.0f;

    #pragma unroll 2
    for (int ks = 0; ks < 8; ++ks) {
        const int k = 2 * ks + khalf;
        const unsigned a0 = smem_base + OFF_A_HI + swz(rA0, k);
        const unsigned a1 = smem_base + OFF_A_HI + swz(rA0 + 16, k);
        const unsigned b0 = smem_base + OFF_W_HI + swz(rB0, k);
        const unsigned b1 = smem_base + OFF_W_HI + swz(rB0 + 16, k);

        unsigned ah[2][4], al[2][4];
        ldsm4(ah[0], a0);
        ldsm4(ah[1], a1);
        ldsm4(al[0], a0 + (OFF_A_LO - OFF_A_HI));
        ldsm4(al[1], a1 + (OFF_A_LO - OFF_A_HI));

        unsigned bh01[4], bh23[4], bl01[4], bl23[4];
        ldsm4(bh01, b0);
        ldsm4(bh23, b1);
        ldsm4(bl01, b0 + (OFF_W_LO - OFF_W_HI));
        ldsm4(bl23, b1 + (OFF_W_LO - OFF_W_HI));

        unsigned bhf[4][2] = {{bh01[0], bh01[2]}, {bh01[1], bh01[3]},
                              {bh23[0], bh23[2]}, {bh23[1], bh23[3]}};
        unsigned blf[4][2] = {{bl01[0], bl01[2]}, {bl01[1], bl01[3]},
                              {bl23[0], bl23[2]}, {bl23[1], bl23[3]}};

        #pragma unroll
        for (int mt = 0; mt < 2; ++mt) {
            #pragma unroll
            for (int nt = 0; nt < 4; ++nt) {
                mma16816(d[mt][nt], ah[mt], bhf[nt][0], bhf[nt][1]);
                mma16816(d[mt][nt], al[mt], bhf[nt][0], bhf[nt][1]);
                mma16816(d[mt][nt], ah[mt], blf[nt][0], blf[nt][1]);
            }
        }
    }

    // ---- epilogue: bias + store ----
    const float* sBias = (const float*)(smem + OFF_BIAS);
    const int g  = lid >> 2;
    const int oc = 2 * (lid & 3);
    #pragma unroll
    for (int mt = 0; mt < 2; ++mt) {
        const int prow = gp0 + 32 * mg + 16 * mt + g;
        #pragma unroll
        for (int nt = 0; nt < 4; ++nt) {
            const int o = 32 * ng + 8 * nt + oc;
            float2 bb = *(const float2*)&sBias[o];
            float2 r0, r1;
            r0.x = d[mt][nt][0] + bb.x;  r0.y = d[mt][nt][1] + bb.y;
            r1.x = d[mt][nt][2] + bb.x;  r1.y = d[mt][nt][3] + bb.y;
            *(float2*)&out[(size_t)prow * OUTD + o]       = r0;
            *(float2*)&out[(size_t)(prow + 8) * OUTD + o] = r1;
        }
    }
}

extern "C" void kernel_launch(void* const* d_in, const int* in_sizes, int n_in,
                              void* d_out, int out_size)
{
    (void)in_sizes; (void)n_in; (void)out_size;
    const float* x    = (const float*)d_in[0];
    const int*   adj  = (const int*)d_in[1];
    const float* W    = (const float*)d_in[2];
    const float* bias = (const float*)d_in[3];
    float* out = (float*)d_out;

    cudaFuncSetAttribute(edgeconv_fused_kernel,
                         cudaFuncAttributeMaxDynamicSharedMemorySize, SMEM_BYTES);

    edgeconv_xs4_kernel<<<(BB * NN * 4) / 256, 256>>>(x);
    edgeconv_prepw_kernel<<<32, 256>>>(W);
    const int tiles = (BB * NN) / TP;   // 1024
    edgeconv_fused_kernel<<<tiles, THREADS, SMEM_BYTES>>>(x, adj, bias, out);
}